// round 3
// baseline (speedup 1.0000x reference)
#include <cuda_runtime.h>
#include <math.h>

#define M 8
#define N 8192
#define KC 256
#define ITERS 6
#define EPSILON 0.01f
#define GAMMA 0.005f
#define LOG2E 1.4426950408889634f

// ---------------- device scratch (static allocation only) ----------------
__device__ float g_a[M * N * KC];      // 64 MB responsibility matrix
__device__ float g_TVs[M * 3 * N];
__device__ float g_L[M * KC];
__device__ float g_W[M * 3 * KC];
__device__ float g_Xnum[3 * KC];
__device__ float g_wn[KC];
__device__ float g_den[KC];
__device__ float4 g_X[KC];             // x,y,z,|x|^2
__device__ float g_Q[KC];
__device__ float g_R[M * 9];
__device__ float g_t[M * 3];
__device__ float g_t0[M * 3];
__device__ float g_beta;

__device__ __forceinline__ float ex2f(float x) {
    float y;
    asm("ex2.approx.ftz.f32 %0, %1;" : "=f"(y) : "f"(x));
    return y;
}

#define WSUM(v) do { \
    v += __shfl_xor_sync(0xffffffffu, (v), 16); \
    v += __shfl_xor_sync(0xffffffffu, (v), 8);  \
    v += __shfl_xor_sync(0xffffffffu, (v), 4);  \
    v += __shfl_xor_sync(0xffffffffu, (v), 2);  \
    v += __shfl_xor_sync(0xffffffffu, (v), 1);  \
} while (0)

// ---------------- init: t0 means, beta, X/Q copies, zero accumulators ----
__global__ void k_pre(const float* Vs, const float* X0, const float* Q0) {
    __shared__ float sh[256];
    int b = blockIdx.x, t = threadIdx.x;
    if (b < 24) {                      // b = m*3+d : mean over n
        const float* p = Vs + b * N;
        float s = 0.f;
        for (int n = t; n < N; n += 256) s += p[n];
        sh[t] = s; __syncthreads();
        for (int o = 128; o > 0; o >>= 1) { if (t < o) sh[t] += sh[t + o]; __syncthreads(); }
        if (t == 0) g_t0[b] = -sh[0] / (float)N;
    } else {                           // beta + copies + zeroing
        float q = (t < KC) ? Q0[t] : 0.f;
        sh[t] = q; __syncthreads();
        for (int o = 128; o > 0; o >>= 1) { if (t < o) sh[t] += sh[t + o]; __syncthreads(); }
        if (t == 0) { float mq = sh[0] / (float)KC; g_beta = GAMMA * mq * sqrtf(mq); }
        if (t < KC) {
            float x = X0[t * 3 + 0], y = X0[t * 3 + 1], z = X0[t * 3 + 2];
            g_X[t] = make_float4(x, y, z, x * x + y * y + z * z);
            g_Q[t] = q;
            g_wn[t] = 0.f; g_den[t] = 0.f;
        }
        for (int i = t; i < M * KC; i += 256) g_L[i] = 0.f;
        for (int i = t; i < M * 3 * KC; i += 256) g_W[i] = 0.f;
        for (int i = t; i < 3 * KC; i += 256) g_Xnum[i] = 0.f;
    }
}

__global__ void k_init(const float* Vs) {
    int idx = blockIdx.x * 256 + threadIdx.x;
    if (idx < M * 3 * N) g_TVs[idx] = Vs[idx] + g_t0[idx / N];
}

// ---------------- a-pass: ds -> exp -> normalize; accumulate L, W --------
__global__ void __launch_bounds__(128) k_apass(const float* Vs) {
    int lane = threadIdx.x & 31, warp = threadIdx.x >> 5;
    int m = blockIdx.x >> 6;                        // 64 blocks per m
    int n0 = ((blockIdx.x & 63) << 7) + (warp << 5);

    float m2x[8], m2y[8], m2z[8], xb[8], nhq[8], q15[8];
#pragma unroll
    for (int j = 0; j < 8; j++) {
        int k = lane + (j << 5);
        float4 xx = g_X[k];
        m2x[j] = -2.f * xx.x; m2y[j] = -2.f * xx.y; m2z[j] = -2.f * xx.z; xb[j] = xx.w;
        float q = g_Q[k];
        nhq[j] = -0.5f * LOG2E * q;
        q15[j] = q * sqrtf(q);
    }
    float beta = g_beta;
    float accL[8], aw0[8], aw1[8], aw2[8];
#pragma unroll
    for (int j = 0; j < 8; j++) { accL[j] = 0.f; aw0[j] = 0.f; aw1[j] = 0.f; aw2[j] = 0.f; }

    const float* tv = g_TVs + m * 3 * N;
    const float* vs = Vs + m * 3 * N;
    for (int n = n0; n < n0 + 32; n++) {
        float tx = tv[n], ty = tv[N + n], tz = tv[2 * N + n];
        float r2 = fmaf(tx, tx, fmaf(ty, ty, tz * tz));
        float ap[8]; float s = 0.f;
#pragma unroll
        for (int j = 0; j < 8; j++) {
            float dd = fmaf(m2x[j], tx, fmaf(m2y[j], ty, fmaf(m2z[j], tz, r2 + xb[j])));
            float e = ex2f(nhq[j] * dd) * q15[j];
            ap[j] = e; s += e;
        }
        WSUM(s);
        float inv = 1.f / (s + beta);
        float v0 = vs[n], v1 = vs[N + n], v2 = vs[2 * N + n];
        float* arow = g_a + (m * N + n) * KC + lane;
#pragma unroll
        for (int j = 0; j < 8; j++) {
            float av = ap[j] * inv;
            accL[j] += av;
            aw0[j] = fmaf(v0, av, aw0[j]);
            aw1[j] = fmaf(v1, av, aw1[j]);
            aw2[j] = fmaf(v2, av, aw2[j]);
            arow[j << 5] = av;
        }
    }
    __shared__ float sh[4 * KC];
    for (int i = threadIdx.x; i < 4 * KC; i += 128) sh[i] = 0.f;
    __syncthreads();
#pragma unroll
    for (int j = 0; j < 8; j++) {
        int k = lane + (j << 5);
        atomicAdd(&sh[k], accL[j]);
        atomicAdd(&sh[KC + k], aw0[j]);
        atomicAdd(&sh[2 * KC + k], aw1[j]);
        atomicAdd(&sh[3 * KC + k], aw2[j]);
    }
    __syncthreads();
    for (int i = threadIdx.x; i < KC; i += 128) {
        atomicAdd(&g_L[m * KC + i], sh[i]);
        atomicAdd(&g_W[(m * 3 + 0) * KC + i], sh[KC + i]);
        atomicAdd(&g_W[(m * 3 + 1) * KC + i], sh[2 * KC + i]);
        atomicAdd(&g_W[(m * 3 + 2) * KC + i], sh[3 * KC + i]);
    }
}

// ---------------- solve: moments, 3x3 SVD (Jacobi on P^T P), R, t, den ---
__global__ void k_solve() {
    int t = threadIdx.x;
    int lane = t & 31, m = t >> 5;   // warp m handles point set m
    float mW0 = 0, mW1 = 0, mW2 = 0, z = 0, mX0 = 0, mX1 = 0, mX2 = 0;
    float p[9];
#pragma unroll
    for (int i = 0; i < 9; i++) p[i] = 0.f;
    for (int j = 0; j < 8; j++) {
        int k = lane + (j << 5);
        float L = g_L[m * KC + k];
        float q = g_Q[k];
        float4 xx = g_X[k];
        float w0 = g_W[(m * 3 + 0) * KC + k] * q;
        float w1 = g_W[(m * 3 + 1) * KC + k] * q;
        float w2 = g_W[(m * 3 + 2) * KC + k] * q;
        mW0 += w0; mW1 += w1; mW2 += w2;
        float b = L * q; z += b;
        mX0 = fmaf(b, xx.x, mX0); mX1 = fmaf(b, xx.y, mX1); mX2 = fmaf(b, xx.z, mX2);
        // P[e][d] += w_d * X_e
        p[0] = fmaf(w0, xx.x, p[0]); p[1] = fmaf(w1, xx.x, p[1]); p[2] = fmaf(w2, xx.x, p[2]);
        p[3] = fmaf(w0, xx.y, p[3]); p[4] = fmaf(w1, xx.y, p[4]); p[5] = fmaf(w2, xx.y, p[5]);
        p[6] = fmaf(w0, xx.z, p[6]); p[7] = fmaf(w1, xx.z, p[7]); p[8] = fmaf(w2, xx.z, p[8]);
    }
    WSUM(mW0); WSUM(mW1); WSUM(mW2); WSUM(z); WSUM(mX0); WSUM(mX1); WSUM(mX2);
#pragma unroll
    for (int i = 0; i < 9; i++) WSUM(p[i]);

    if (lane == 0) {
        float iz = 1.f / z;
        float mXa[3] = { mX0, mX1, mX2 }, mWa[3] = { mW0, mW1, mW2 };
        float P[9];
        for (int e = 0; e < 3; e++)
            for (int d = 0; d < 3; d++)
                P[e * 3 + d] = p[e * 3 + d] - mXa[e] * mWa[d] * iz;
        // A = P^T P (symmetric)
        float A[9];
        for (int d1 = 0; d1 < 3; d1++)
            for (int d2 = 0; d2 < 3; d2++) {
                float s2 = 0.f;
                for (int e = 0; e < 3; e++) s2 += P[e * 3 + d1] * P[e * 3 + d2];
                A[d1 * 3 + d2] = s2;
            }
        float V[9] = { 1, 0, 0, 0, 1, 0, 0, 0, 1 };
        for (int sweep = 0; sweep < 15; sweep++) {
            for (int pair = 0; pair < 3; pair++) {
                int pp = (pair == 2) ? 1 : 0;
                int qq = (pair == 0) ? 1 : 2;
                float apq = A[pp * 3 + qq];
                if (fabsf(apq) < 1e-30f) continue;
                float app = A[pp * 3 + pp], aqq = A[qq * 3 + qq];
                float theta = 0.5f * (aqq - app) / apq;
                float tj = copysignf(1.f, theta) / (fabsf(theta) + sqrtf(1.f + theta * theta));
                float c = rsqrtf(1.f + tj * tj);
                float sj = tj * c;
                for (int i = 0; i < 3; i++) {
                    float aip = A[i * 3 + pp], aiq = A[i * 3 + qq];
                    A[i * 3 + pp] = c * aip - sj * aiq;
                    A[i * 3 + qq] = sj * aip + c * aiq;
                }
                for (int i = 0; i < 3; i++) {
                    float api = A[pp * 3 + i], aqi = A[qq * 3 + i];
                    A[pp * 3 + i] = c * api - sj * aqi;
                    A[qq * 3 + i] = sj * api + c * aqi;
                }
                for (int i = 0; i < 3; i++) {
                    float vip = V[i * 3 + pp], viq = V[i * 3 + qq];
                    V[i * 3 + pp] = c * vip - sj * viq;
                    V[i * 3 + qq] = sj * vip + c * viq;
                }
            }
        }
        // sort eigenpairs descending
        float ev[3] = { A[0], A[4], A[8] };
        int ord[3] = { 0, 1, 2 };
        if (ev[ord[0]] < ev[ord[1]]) { int tt = ord[0]; ord[0] = ord[1]; ord[1] = tt; }
        if (ev[ord[1]] < ev[ord[2]]) { int tt = ord[1]; ord[1] = ord[2]; ord[2] = tt; }
        if (ev[ord[0]] < ev[ord[1]]) { int tt = ord[0]; ord[0] = ord[1]; ord[1] = tt; }
        float Vm[9];
        for (int i = 0; i < 3; i++)
            for (int c2 = 0; c2 < 3; c2++)
                Vm[i * 3 + c2] = V[i * 3 + ord[c2]];
        float det = Vm[0] * (Vm[4] * Vm[8] - Vm[5] * Vm[7])
                  - Vm[1] * (Vm[3] * Vm[8] - Vm[5] * Vm[6])
                  + Vm[2] * (Vm[3] * Vm[7] - Vm[4] * Vm[6]);
        if (det < 0.f) { Vm[2] = -Vm[2]; Vm[5] = -Vm[5]; Vm[8] = -Vm[8]; }
        // u1 = normalize(P v1); u2 = orthonormalize(P v2); u3 = u1 x u2
        float u1[3], u2[3], u3[3];
        for (int e = 0; e < 3; e++) {
            u1[e] = P[e * 3 + 0] * Vm[0] + P[e * 3 + 1] * Vm[3] + P[e * 3 + 2] * Vm[6];
            u2[e] = P[e * 3 + 0] * Vm[1] + P[e * 3 + 1] * Vm[4] + P[e * 3 + 2] * Vm[7];
        }
        float n1 = rsqrtf(u1[0] * u1[0] + u1[1] * u1[1] + u1[2] * u1[2]);
        for (int e = 0; e < 3; e++) u1[e] *= n1;
        float d12 = u1[0] * u2[0] + u1[1] * u2[1] + u1[2] * u2[2];
        for (int e = 0; e < 3; e++) u2[e] -= d12 * u1[e];
        float n2 = rsqrtf(u2[0] * u2[0] + u2[1] * u2[1] + u2[2] * u2[2]);
        for (int e = 0; e < 3; e++) u2[e] *= n2;
        u3[0] = u1[1] * u2[2] - u1[2] * u2[1];
        u3[1] = u1[2] * u2[0] - u1[0] * u2[2];
        u3[2] = u1[0] * u2[1] - u1[1] * u2[0];
        float R[9];
        for (int i = 0; i < 3; i++)
            for (int jj = 0; jj < 3; jj++)
                R[i * 3 + jj] = u1[i] * Vm[jj * 3 + 0] + u2[i] * Vm[jj * 3 + 1] + u3[i] * Vm[jj * 3 + 2];
        for (int i = 0; i < 9; i++) g_R[m * 9 + i] = R[i];
        for (int i = 0; i < 3; i++)
            g_t[m * 3 + i] = (mXa[i] - (R[i * 3 + 0] * mW0 + R[i * 3 + 1] * mW1 + R[i * 3 + 2] * mW2)) * iz;
    }
    __syncthreads();
    if (t < KC) {
        float ds = 0.f;
        for (int mm = 0; mm < M; mm++) ds += g_L[mm * KC + t];
        g_den[t] = ds;
    }
    __syncthreads();
    for (int i = t; i < M * KC; i += 256) g_L[i] = 0.f;          // ready for next a-pass
    for (int i = t; i < M * 3 * KC; i += 256) g_W[i] = 0.f;
}

// ---------------- TVs = R Vs + t ----------------
__global__ void k_tvs(const float* Vs) {
    int idx = blockIdx.x * 256 + threadIdx.x;
    if (idx >= M * 3 * N) return;
    int md = idx / N, n = idx - md * N;
    int m = md / 3;
    const float* v = Vs + m * 3 * N;
    const float* R = g_R + m * 9 + (md - 3 * m) * 3;
    g_TVs[idx] = fmaf(R[0], v[n], fmaf(R[1], v[N + n], fmaf(R[2], v[2 * N + n], g_t[md])));
}

// ---------------- pass 2: mode 0 = wn accumulation, mode 1 = Xnum --------
__global__ void __launch_bounds__(128) k_pass2(int mode) {
    int lane = threadIdx.x & 31, warp = threadIdx.x >> 5;
    int m = blockIdx.x >> 6;
    int n0 = ((blockIdx.x & 63) << 7) + (warp << 5);
    float m2x[8], m2y[8], m2z[8], xb[8];
    if (mode == 0) {
#pragma unroll
        for (int j = 0; j < 8; j++) {
            float4 xx = g_X[lane + (j << 5)];
            m2x[j] = -2.f * xx.x; m2y[j] = -2.f * xx.y; m2z[j] = -2.f * xx.z; xb[j] = xx.w;
        }
    }
    float a0[8], a1[8], a2[8];
#pragma unroll
    for (int j = 0; j < 8; j++) { a0[j] = 0.f; a1[j] = 0.f; a2[j] = 0.f; }
    const float* tv = g_TVs + m * 3 * N;
    for (int n = n0; n < n0 + 32; n++) {
        float tx = tv[n], ty = tv[N + n], tz = tv[2 * N + n];
        const float* arow = g_a + (m * N + n) * KC + lane;
        if (mode == 0) {
            float r2 = fmaf(tx, tx, fmaf(ty, ty, tz * tz));
#pragma unroll
            for (int j = 0; j < 8; j++) {
                float a = arow[j << 5];
                float dd = fmaf(m2x[j], tx, fmaf(m2y[j], ty, fmaf(m2z[j], tz, r2 + xb[j])));
                a0[j] = fmaf(a, dd, a0[j]);
            }
        } else {
#pragma unroll
            for (int j = 0; j < 8; j++) {
                float a = arow[j << 5];
                a0[j] = fmaf(tx, a, a0[j]);
                a1[j] = fmaf(ty, a, a1[j]);
                a2[j] = fmaf(tz, a, a2[j]);
            }
        }
    }
    __shared__ float sh[3 * KC];
    int lim = (mode == 0) ? KC : 3 * KC;
    for (int i = threadIdx.x; i < lim; i += 128) sh[i] = 0.f;
    __syncthreads();
#pragma unroll
    for (int j = 0; j < 8; j++) {
        int k = lane + (j << 5);
        atomicAdd(&sh[k], a0[j]);
        if (mode != 0) { atomicAdd(&sh[KC + k], a1[j]); atomicAdd(&sh[2 * KC + k], a2[j]); }
    }
    __syncthreads();
    if (mode == 0) {
        for (int i = threadIdx.x; i < KC; i += 128) atomicAdd(&g_wn[i], sh[i]);
    } else {
        for (int i = threadIdx.x; i < 3 * KC; i += 128) atomicAdd(&g_Xnum[i], sh[i]);
    }
}

__global__ void k_xupd() {
    int k = threadIdx.x;
    if (k < KC) {
        float inv = 1.f / g_den[k];
        float x = g_Xnum[k] * inv, y = g_Xnum[KC + k] * inv, zz = g_Xnum[2 * KC + k] * inv;
        g_X[k] = make_float4(x, y, zz, x * x + y * y + zz * zz);
        g_Xnum[k] = 0.f; g_Xnum[KC + k] = 0.f; g_Xnum[2 * KC + k] = 0.f;
    }
}

__global__ void k_qupd() {
    int k = threadIdx.x;
    if (k < KC) {
        float den = g_den[k], wn = g_wn[k];
        g_Q[k] = 3.f * den / (wn + 3.f * den * EPSILON);
        g_wn[k] = 0.f;
    }
}

// ---------------- gather outputs: concat(TVs, R, t, X) -------------------
__global__ void k_out(float* out) {
    int idx = blockIdx.x * 256 + threadIdx.x;
    const int nTV = M * 3 * N, nR = M * 9, nT = M * 3, nX = KC * 3;
    if (idx < nTV) out[idx] = g_TVs[idx];
    else if (idx < nTV + nR) out[idx] = g_R[idx - nTV];
    else if (idx < nTV + nR + nT) out[idx] = g_t[idx - nTV - nR];
    else if (idx < nTV + nR + nT + nX) {
        int r = idx - nTV - nR - nT;
        int k = r / 3, d = r - 3 * k;
        float4 xx = g_X[k];
        out[idx] = (d == 0) ? xx.x : ((d == 1) ? xx.y : xx.z);
    }
}

extern "C" void kernel_launch(void* const* d_in, const int* in_sizes, int n_in,
                              void* d_out, int out_size) {
    const float* Vs = (const float*)d_in[0];
    const float* X0 = (const float*)d_in[1];
    const float* Q0 = (const float*)d_in[2];
    float* out = (float*)d_out;

    k_pre<<<25, 256>>>(Vs, X0, Q0);
    k_init<<<(M * 3 * N) / 256, 256>>>(Vs);

    for (int i = 0; i < ITERS; i++) {
        k_apass<<<512, 128>>>(Vs);
        k_solve<<<1, 256>>>();
        k_tvs<<<(M * 3 * N) / 256, 256>>>(Vs);
        if (i > 1) {                                  // FIX_CLUSTER_POS_ITER = 1
            k_pass2<<<512, 128>>>(1);                 // Xnum
            k_xupd<<<1, 256>>>();
            if (i < ITERS - 1) {
                k_pass2<<<512, 128>>>(0);             // wn with updated X
                k_qupd<<<1, 256>>>();
            }
        } else {
            k_pass2<<<512, 128>>>(0);                 // wn, X unchanged
            k_qupd<<<1, 256>>>();
        }
    }
    int total = M * 3 * N + M * 9 + M * 3 + KC * 3;
    k_out<<<(total + 255) / 256, 256>>>(out);
}

// round 4
// speedup vs baseline: 1.1006x; 1.1006x over previous
#include <cuda_runtime.h>
#include <math.h>

#define M 8
#define N 8192
#define KC 256
#define ITERS 6
#define EPSILON 0.01f
#define GAMMA 0.005f
#define LOG2E 1.4426950408889634f

// ---------------- device scratch (static allocation only) ----------------
__device__ float g_a[M * N * KC];      // 64 MB responsibility matrix
__device__ float g_L[M * KC];
__device__ float g_W[M * 3 * KC];
__device__ float g_Xnum[3 * KC];       // T_k = sum_{m,n} a * tv
__device__ float g_S2[KC];             // S2_k = sum_{m,n} a * |tv|^2
__device__ float g_den[KC];
__device__ float4 g_X[KC];             // x,y,z,|x|^2
__device__ float g_Q[KC];
__device__ float g_R[M * 9];
__device__ float g_t[M * 3];
__device__ float g_beta;

__device__ __forceinline__ float ex2f(float x) {
    float y;
    asm("ex2.approx.ftz.f32 %0, %1;" : "=f"(y) : "f"(x));
    return y;
}

#define WSUM(v) do { \
    v += __shfl_xor_sync(0xffffffffu, (v), 16); \
    v += __shfl_xor_sync(0xffffffffu, (v), 8);  \
    v += __shfl_xor_sync(0xffffffffu, (v), 4);  \
    v += __shfl_xor_sync(0xffffffffu, (v), 2);  \
    v += __shfl_xor_sync(0xffffffffu, (v), 1);  \
} while (0)

// ---------------- init ----------------
__global__ void k_pre(const float* Vs, const float* X0, const float* Q0) {
    __shared__ float sh[256];
    int b = blockIdx.x, t = threadIdx.x;
    if (b < 24) {                      // b = m*3+d : mean over n -> g_t
        const float* p = Vs + b * N;
        float s = 0.f;
        for (int n = t; n < N; n += 256) s += p[n];
        sh[t] = s; __syncthreads();
        for (int o = 128; o > 0; o >>= 1) { if (t < o) sh[t] += sh[t + o]; __syncthreads(); }
        if (t == 0) g_t[b] = -sh[0] / (float)N;
    } else {
        float q = (t < KC) ? Q0[t] : 0.f;
        sh[t] = q; __syncthreads();
        for (int o = 128; o > 0; o >>= 1) { if (t < o) sh[t] += sh[t + o]; __syncthreads(); }
        if (t == 0) { float mq = sh[0] / (float)KC; g_beta = GAMMA * mq * sqrtf(mq); }
        if (t < KC) {
            float x = X0[t * 3 + 0], y = X0[t * 3 + 1], z = X0[t * 3 + 2];
            g_X[t] = make_float4(x, y, z, x * x + y * y + z * z);
            g_Q[t] = q;
            g_S2[t] = 0.f; g_den[t] = 0.f;
        }
        if (t < 72) {                  // R = I per m
            int m = t / 9, i = t - 9 * m;
            g_R[t] = (i == 0 || i == 4 || i == 8) ? 1.f : 0.f;
        }
        for (int i = t; i < M * KC; i += 256) g_L[i] = 0.f;
        for (int i = t; i < M * 3 * KC; i += 256) g_W[i] = 0.f;
        for (int i = t; i < 3 * KC; i += 256) g_Xnum[i] = 0.f;
    }
}

// ---------------- a-pass: deferred X/Q update + ds->exp->softmax; L,W ----
__global__ void __launch_bounds__(128) k_apass(const float* __restrict__ Vs, int prev) {
    int lane = threadIdx.x & 31, warp = threadIdx.x >> 5;
    int m = blockIdx.x >> 7;                        // 128 blocks per m
    int n0 = ((blockIdx.x & 127) << 6) + (warp << 4);

    float cx[8], cy[8], cz[8], cc[8], nq[8], q15[8];
#pragma unroll
    for (int j = 0; j < 8; j++) {
        int k = lane + (j << 5);
        float x, y, z, xw, q;
        if (prev < 0) {
            float4 xx = g_X[k]; x = xx.x; y = xx.y; z = xx.z; xw = xx.w;
            q = g_Q[k];
        } else {
            float den = g_den[k];
            float Tx = g_Xnum[k], Ty = g_Xnum[KC + k], Tz = g_Xnum[2 * KC + k];
            float S2 = g_S2[k];
            float inv = 1.f / den;
            float wn;
            if (prev >= 2) {                         // FIX_CLUSTER_POS_ITER = 1
                x = Tx * inv; y = Ty * inv; z = Tz * inv;
                xw = x * x + y * y + z * z;
                wn = S2 - (Tx * Tx + Ty * Ty + Tz * Tz) * inv;
            } else {
                float4 xo = g_X[k]; x = xo.x; y = xo.y; z = xo.z; xw = xo.w;
                wn = fmaf(den, xw, S2) - 2.f * (x * Tx + y * Ty + z * Tz);
            }
            q = 3.f * den / (wn + 3.f * den * EPSILON);
            if (blockIdx.x == 0 && warp == 0) {      // publish for k_solve
                g_Q[k] = q;
                if (prev >= 2) g_X[k] = make_float4(x, y, z, xw);
            }
        }
        float nhq = -0.5f * LOG2E * q;
        nq[j] = nhq;
        cx[j] = -2.f * nhq * x; cy[j] = -2.f * nhq * y; cz[j] = -2.f * nhq * z;
        cc[j] = nhq * xw;
        q15[j] = q * sqrtf(q);
    }
    float beta = g_beta;
    float accL[8], aw0[8], aw1[8], aw2[8];
#pragma unroll
    for (int j = 0; j < 8; j++) { accL[j] = 0.f; aw0[j] = 0.f; aw1[j] = 0.f; aw2[j] = 0.f; }

    const float* vs = Vs + m * 3 * N;
    const float* Rm = g_R + m * 9;
    float r0 = Rm[0], r1 = Rm[1], r2c = Rm[2], r3 = Rm[3], r4 = Rm[4], r5 = Rm[5],
          r6 = Rm[6], r7 = Rm[7], r8 = Rm[8];
    float tt0 = g_t[m * 3 + 0], tt1 = g_t[m * 3 + 1], tt2 = g_t[m * 3 + 2];

    for (int n = n0; n < n0 + 16; n++) {
        float v0 = vs[n], v1 = vs[N + n], v2 = vs[2 * N + n];
        float tx = fmaf(r0, v0, fmaf(r1, v1, fmaf(r2c, v2, tt0)));
        float ty = fmaf(r3, v0, fmaf(r4, v1, fmaf(r5, v2, tt1)));
        float tz = fmaf(r6, v0, fmaf(r7, v1, fmaf(r8, v2, tt2)));
        float rr = fmaf(tx, tx, fmaf(ty, ty, tz * tz));
        float ap[8]; float s = 0.f;
#pragma unroll
        for (int j = 0; j < 8; j++) {
            float arg = fmaf(cx[j], tx, fmaf(cy[j], ty, fmaf(cz[j], tz, fmaf(nq[j], rr, cc[j]))));
            float e = ex2f(arg) * q15[j];
            ap[j] = e; s += e;
        }
        WSUM(s);
        float inv = 1.f / (s + beta);
        float* arow = g_a + (m * N + n) * KC + lane;
#pragma unroll
        for (int j = 0; j < 8; j++) {
            float av = ap[j] * inv;
            accL[j] += av;
            aw0[j] = fmaf(v0, av, aw0[j]);
            aw1[j] = fmaf(v1, av, aw1[j]);
            aw2[j] = fmaf(v2, av, aw2[j]);
            arow[j << 5] = av;
        }
    }
    __shared__ float sh[4 * KC];
    for (int i = threadIdx.x; i < 4 * KC; i += 128) sh[i] = 0.f;
    __syncthreads();
#pragma unroll
    for (int j = 0; j < 8; j++) {
        int k = lane + (j << 5);
        atomicAdd(&sh[k], accL[j]);
        atomicAdd(&sh[KC + k], aw0[j]);
        atomicAdd(&sh[2 * KC + k], aw1[j]);
        atomicAdd(&sh[3 * KC + k], aw2[j]);
    }
    __syncthreads();
    for (int i = threadIdx.x; i < KC; i += 128) {
        atomicAdd(&g_L[m * KC + i], sh[i]);
        atomicAdd(&g_W[(m * 3 + 0) * KC + i], sh[KC + i]);
        atomicAdd(&g_W[(m * 3 + 1) * KC + i], sh[2 * KC + i]);
        atomicAdd(&g_W[(m * 3 + 2) * KC + i], sh[3 * KC + i]);
    }
}

// Jacobi rotation with COMPILE-TIME indices (keeps A/V in registers)
#define JROT(P_, Q_) do { \
    float apq = A[P_][Q_]; \
    if (fabsf(apq) > 1e-30f) { \
        float theta = 0.5f * (A[Q_][Q_] - A[P_][P_]) / apq; \
        float tj = copysignf(1.f, theta) / (fabsf(theta) + sqrtf(fmaf(theta, theta, 1.f))); \
        float c = rsqrtf(fmaf(tj, tj, 1.f)); \
        float sj = tj * c; \
        _Pragma("unroll") \
        for (int i_ = 0; i_ < 3; i_++) { \
            float aip = A[i_][P_], aiq = A[i_][Q_]; \
            A[i_][P_] = c * aip - sj * aiq; \
            A[i_][Q_] = sj * aip + c * aiq; \
        } \
        _Pragma("unroll") \
        for (int i_ = 0; i_ < 3; i_++) { \
            float api = A[P_][i_], aqi = A[Q_][i_]; \
            A[P_][i_] = c * api - sj * aqi; \
            A[Q_][i_] = sj * api + c * aqi; \
        } \
        _Pragma("unroll") \
        for (int i_ = 0; i_ < 3; i_++) { \
            float vip = V[i_][P_], viq = V[i_][Q_]; \
            V[i_][P_] = c * vip - sj * viq; \
            V[i_][Q_] = sj * vip + c * viq; \
        } \
    } \
} while (0)

#define VSWAPC(C0_, C1_) do { \
    float tmp_; \
    tmp_ = V[0][C0_]; V[0][C0_] = V[0][C1_]; V[0][C1_] = tmp_; \
    tmp_ = V[1][C0_]; V[1][C0_] = V[1][C1_]; V[1][C1_] = tmp_; \
    tmp_ = V[2][C0_]; V[2][C0_] = V[2][C1_]; V[2][C1_] = tmp_; \
} while (0)

// ---------------- solve: moments, 3x3 SVD, R, t, den; zero accumulators --
__global__ void k_solve() {
    int t = threadIdx.x;
    int lane = t & 31, m = t >> 5;   // warp m handles point set m
    float mW0 = 0, mW1 = 0, mW2 = 0, z = 0, mX0 = 0, mX1 = 0, mX2 = 0;
    float p[9];
#pragma unroll
    for (int i = 0; i < 9; i++) p[i] = 0.f;
#pragma unroll
    for (int j = 0; j < 8; j++) {
        int k = lane + (j << 5);
        float L = g_L[m * KC + k];
        float q = g_Q[k];
        float4 xx = g_X[k];
        float w0 = g_W[(m * 3 + 0) * KC + k] * q;
        float w1 = g_W[(m * 3 + 1) * KC + k] * q;
        float w2 = g_W[(m * 3 + 2) * KC + k] * q;
        mW0 += w0; mW1 += w1; mW2 += w2;
        float b = L * q; z += b;
        mX0 = fmaf(b, xx.x, mX0); mX1 = fmaf(b, xx.y, mX1); mX2 = fmaf(b, xx.z, mX2);
        p[0] = fmaf(w0, xx.x, p[0]); p[1] = fmaf(w1, xx.x, p[1]); p[2] = fmaf(w2, xx.x, p[2]);
        p[3] = fmaf(w0, xx.y, p[3]); p[4] = fmaf(w1, xx.y, p[4]); p[5] = fmaf(w2, xx.y, p[5]);
        p[6] = fmaf(w0, xx.z, p[6]); p[7] = fmaf(w1, xx.z, p[7]); p[8] = fmaf(w2, xx.z, p[8]);
    }
    WSUM(mW0); WSUM(mW1); WSUM(mW2); WSUM(z); WSUM(mX0); WSUM(mX1); WSUM(mX2);
#pragma unroll
    for (int i = 0; i < 9; i++) WSUM(p[i]);

    if (lane == 0) {
        float iz = 1.f / z;
        float mXa[3] = { mX0, mX1, mX2 }, mWa[3] = { mW0, mW1, mW2 };
        float P[3][3];
#pragma unroll
        for (int e = 0; e < 3; e++)
#pragma unroll
            for (int d = 0; d < 3; d++)
                P[e][d] = p[e * 3 + d] - mXa[e] * mWa[d] * iz;
        float A[3][3];
#pragma unroll
        for (int d1 = 0; d1 < 3; d1++)
#pragma unroll
            for (int d2 = 0; d2 < 3; d2++) {
                float s2 = 0.f;
#pragma unroll
                for (int e = 0; e < 3; e++) s2 += P[e][d1] * P[e][d2];
                A[d1][d2] = s2;
            }
        float V[3][3] = { {1, 0, 0}, {0, 1, 0}, {0, 0, 1} };
#pragma unroll
        for (int sweep = 0; sweep < 8; sweep++) {
            JROT(0, 1);
            JROT(0, 2);
            JROT(1, 2);
        }
        // sort eigenpairs descending via explicit column swaps
        float e0 = A[0][0], e1 = A[1][1], e2 = A[2][2];
        if (e0 < e1) { float tm = e0; e0 = e1; e1 = tm; VSWAPC(0, 1); }
        if (e1 < e2) { float tm = e1; e1 = e2; e2 = tm; VSWAPC(1, 2); }
        if (e0 < e1) { float tm = e0; e0 = e1; e1 = tm; VSWAPC(0, 1); }
        float det = V[0][0] * (V[1][1] * V[2][2] - V[1][2] * V[2][1])
                  - V[0][1] * (V[1][0] * V[2][2] - V[1][2] * V[2][0])
                  + V[0][2] * (V[1][0] * V[2][1] - V[1][1] * V[2][0]);
        if (det < 0.f) { V[0][2] = -V[0][2]; V[1][2] = -V[1][2]; V[2][2] = -V[2][2]; }
        // u1 = normalize(P v1); u2 = gram-schmidt(P v2); u3 = u1 x u2
        float u1[3], u2[3], u3[3];
#pragma unroll
        for (int e = 0; e < 3; e++) {
            u1[e] = P[e][0] * V[0][0] + P[e][1] * V[1][0] + P[e][2] * V[2][0];
            u2[e] = P[e][0] * V[0][1] + P[e][1] * V[1][1] + P[e][2] * V[2][1];
        }
        float n1 = rsqrtf(u1[0] * u1[0] + u1[1] * u1[1] + u1[2] * u1[2]);
#pragma unroll
        for (int e = 0; e < 3; e++) u1[e] *= n1;
        float d12 = u1[0] * u2[0] + u1[1] * u2[1] + u1[2] * u2[2];
#pragma unroll
        for (int e = 0; e < 3; e++) u2[e] -= d12 * u1[e];
        float n2 = rsqrtf(u2[0] * u2[0] + u2[1] * u2[1] + u2[2] * u2[2]);
#pragma unroll
        for (int e = 0; e < 3; e++) u2[e] *= n2;
        u3[0] = u1[1] * u2[2] - u1[2] * u2[1];
        u3[1] = u1[2] * u2[0] - u1[0] * u2[2];
        u3[2] = u1[0] * u2[1] - u1[1] * u2[0];
        float R[9];
#pragma unroll
        for (int i = 0; i < 3; i++)
#pragma unroll
            for (int jj = 0; jj < 3; jj++)
                R[i * 3 + jj] = u1[i] * V[jj][0] + u2[i] * V[jj][1] + u3[i] * V[jj][2];
#pragma unroll
        for (int i = 0; i < 9; i++) g_R[m * 9 + i] = R[i];
#pragma unroll
        for (int i = 0; i < 3; i++)
            g_t[m * 3 + i] = (mXa[i] - (R[i * 3 + 0] * mW0 + R[i * 3 + 1] * mW1 + R[i * 3 + 2] * mW2)) * iz;
    }
    __syncthreads();
    if (t < KC) {
        float ds = 0.f;
#pragma unroll
        for (int mm = 0; mm < M; mm++) ds += g_L[mm * KC + t];
        g_den[t] = ds;
    }
    __syncthreads();
    for (int i = t; i < M * KC; i += 256) g_L[i] = 0.f;          // ready for next a-pass
    for (int i = t; i < M * 3 * KC; i += 256) g_W[i] = 0.f;
    if (t < KC) g_S2[t] = 0.f;                                   // ready for pass2
    for (int i = t; i < 3 * KC; i += 256) g_Xnum[i] = 0.f;
}

// ---------------- pass 2: accumulate T = sum a*tv, S2 = sum a*|tv|^2 -----
__global__ void __launch_bounds__(128) k_pass2(const float* __restrict__ Vs) {
    int lane = threadIdx.x & 31, warp = threadIdx.x >> 5;
    int m = blockIdx.x >> 7;
    int n0 = ((blockIdx.x & 127) << 6) + (warp << 4);

    const float* vs = Vs + m * 3 * N;
    const float* Rm = g_R + m * 9;
    float r0 = Rm[0], r1 = Rm[1], r2c = Rm[2], r3 = Rm[3], r4 = Rm[4], r5 = Rm[5],
          r6 = Rm[6], r7 = Rm[7], r8 = Rm[8];
    float tt0 = g_t[m * 3 + 0], tt1 = g_t[m * 3 + 1], tt2 = g_t[m * 3 + 2];

    float a0[8], a1[8], a2[8], aS[8];
#pragma unroll
    for (int j = 0; j < 8; j++) { a0[j] = 0.f; a1[j] = 0.f; a2[j] = 0.f; aS[j] = 0.f; }

    for (int n = n0; n < n0 + 16; n++) {
        float v0 = vs[n], v1 = vs[N + n], v2 = vs[2 * N + n];
        float tx = fmaf(r0, v0, fmaf(r1, v1, fmaf(r2c, v2, tt0)));
        float ty = fmaf(r3, v0, fmaf(r4, v1, fmaf(r5, v2, tt1)));
        float tz = fmaf(r6, v0, fmaf(r7, v1, fmaf(r8, v2, tt2)));
        float rr = fmaf(tx, tx, fmaf(ty, ty, tz * tz));
        const float* arow = g_a + (m * N + n) * KC + lane;
#pragma unroll
        for (int j = 0; j < 8; j++) {
            float a = arow[j << 5];
            a0[j] = fmaf(tx, a, a0[j]);
            a1[j] = fmaf(ty, a, a1[j]);
            a2[j] = fmaf(tz, a, a2[j]);
            aS[j] = fmaf(rr, a, aS[j]);
        }
    }
    __shared__ float sh[4 * KC];
    for (int i = threadIdx.x; i < 4 * KC; i += 128) sh[i] = 0.f;
    __syncthreads();
#pragma unroll
    for (int j = 0; j < 8; j++) {
        int k = lane + (j << 5);
        atomicAdd(&sh[k], a0[j]);
        atomicAdd(&sh[KC + k], a1[j]);
        atomicAdd(&sh[2 * KC + k], a2[j]);
        atomicAdd(&sh[3 * KC + k], aS[j]);
    }
    __syncthreads();
    for (int i = threadIdx.x; i < KC; i += 128) {
        atomicAdd(&g_Xnum[i], sh[i]);
        atomicAdd(&g_Xnum[KC + i], sh[KC + i]);
        atomicAdd(&g_Xnum[2 * KC + i], sh[2 * KC + i]);
        atomicAdd(&g_S2[i], sh[3 * KC + i]);
    }
}

// ---------------- gather outputs: concat(TVs, R, t, X) -------------------
__global__ void k_out(float* out, const float* __restrict__ Vs) {
    int idx = blockIdx.x * 256 + threadIdx.x;
    const int nTV = M * 3 * N, nR = M * 9, nT = M * 3, nX = KC * 3;
    if (idx < nTV) {
        int md = idx / N, n = idx - md * N;
        int m = md / 3, d = md - 3 * m;
        const float* v = Vs + m * 3 * N;
        const float* R = g_R + m * 9 + d * 3;
        out[idx] = fmaf(R[0], v[n], fmaf(R[1], v[N + n], fmaf(R[2], v[2 * N + n], g_t[md])));
    } else if (idx < nTV + nR) out[idx] = g_R[idx - nTV];
    else if (idx < nTV + nR + nT) out[idx] = g_t[idx - nTV - nR];
    else if (idx < nTV + nR + nT + nX) {
        int r = idx - nTV - nR - nT;
        int k = r / 3, d = r - 3 * k;
        out[idx] = g_Xnum[d * KC + k] / g_den[k];   // deferred final X update
    }
}

extern "C" void kernel_launch(void* const* d_in, const int* in_sizes, int n_in,
                              void* d_out, int out_size) {
    const float* Vs = (const float*)d_in[0];
    const float* X0 = (const float*)d_in[1];
    const float* Q0 = (const float*)d_in[2];
    float* out = (float*)d_out;

    k_pre<<<25, 256>>>(Vs, X0, Q0);

    for (int i = 0; i < ITERS; i++) {
        k_apass<<<1024, 128>>>(Vs, i - 1);   // performs deferred X/Q update of iter i-1
        k_solve<<<1, 256>>>();
        k_pass2<<<1024, 128>>>(Vs);
    }
    int total = M * 3 * N + M * 9 + M * 3 + KC * 3;
    k_out<<<(total + 255) / 256, 256>>>(out, Vs);
}

// round 6
// speedup vs baseline: 1.1444x; 1.0398x over previous
#include <cuda_runtime.h>
#include <math.h>

#define M 8
#define N 8192
#define KC 256
#define ITERS 6
#define EPSILON 0.01f
#define GAMMA 0.005f
#define LOG2E 1.4426950408889634f

// ---------------- device scratch (static allocation only) ----------------
__device__ float g_L[M * KC];          // sum_n a
__device__ float g_W[M * 3 * KC];      // sum_n a * v   (no Q factor)
__device__ float g_S2v[M * KC];        // sum_n a * |v|^2
__device__ float4 g_X[KC];             // x,y,z,|x|^2
__device__ float g_Q[KC];
__device__ float g_R[M * 9];
__device__ float g_t[M * 3];
__device__ float g_beta;

__device__ __forceinline__ float ex2f(float x) {
    float y;
    asm("ex2.approx.ftz.f32 %0, %1;" : "=f"(y) : "f"(x));
    return y;
}

#define WSUM(v) do { \
    v += __shfl_xor_sync(0xffffffffu, (v), 16); \
    v += __shfl_xor_sync(0xffffffffu, (v), 8);  \
    v += __shfl_xor_sync(0xffffffffu, (v), 4);  \
    v += __shfl_xor_sync(0xffffffffu, (v), 2);  \
    v += __shfl_xor_sync(0xffffffffu, (v), 1);  \
} while (0)

// ---------------- init ----------------
__global__ void k_pre(const float* Vs, const float* X0, const float* Q0) {
    __shared__ float sh[256];
    int b = blockIdx.x, t = threadIdx.x;
    if (b < 24) {                      // b = m*3+d : mean over n -> g_t
        const float* p = Vs + b * N;
        float s = 0.f;
        for (int n = t; n < N; n += 256) s += p[n];
        sh[t] = s; __syncthreads();
        for (int o = 128; o > 0; o >>= 1) { if (t < o) sh[t] += sh[t + o]; __syncthreads(); }
        if (t == 0) g_t[b] = -sh[0] / (float)N;
    } else {
        float q = (t < KC) ? Q0[t] : 0.f;
        sh[t] = q; __syncthreads();
        for (int o = 128; o > 0; o >>= 1) { if (t < o) sh[t] += sh[t + o]; __syncthreads(); }
        if (t == 0) { float mq = sh[0] / (float)KC; g_beta = GAMMA * mq * sqrtf(mq); }
        if (t < KC) {
            float x = X0[t * 3 + 0], y = X0[t * 3 + 1], z = X0[t * 3 + 2];
            g_X[t] = make_float4(x, y, z, x * x + y * y + z * z);
            g_Q[t] = q;
        }
        if (t < 72) {                  // R = I per m
            int m = t / 9, i = t - 9 * m;
            g_R[t] = (i == 0 || i == 4 || i == 8) ? 1.f : 0.f;
        }
        for (int i = t; i < M * KC; i += 256) { g_L[i] = 0.f; g_S2v[i] = 0.f; }
        for (int i = t; i < M * 3 * KC; i += 256) g_W[i] = 0.f;
    }
}

// ------- a-pass: tv = R v + t on the fly; accumulate L, W, S2v only ------
__global__ void __launch_bounds__(128) k_apass(const float* __restrict__ Vs) {
    int lane = threadIdx.x & 31, warp = threadIdx.x >> 5;
    int m = blockIdx.x >> 7;                        // 128 blocks per m
    int n0 = ((blockIdx.x & 127) << 6) + (warp << 4);

    float cx[8], cy[8], cz[8], cc[8], nq[8], q15[8];
#pragma unroll
    for (int j = 0; j < 8; j++) {
        int k = lane + (j << 5);
        float4 xx = g_X[k];
        float q = g_Q[k];
        float nhq = -0.5f * LOG2E * q;
        nq[j] = nhq;
        cx[j] = -2.f * nhq * xx.x; cy[j] = -2.f * nhq * xx.y; cz[j] = -2.f * nhq * xx.z;
        cc[j] = nhq * xx.w;
        q15[j] = q * sqrtf(q);
    }
    float beta = g_beta;
    float accL[8], aw0[8], aw1[8], aw2[8], aS[8];
#pragma unroll
    for (int j = 0; j < 8; j++) { accL[j] = 0.f; aw0[j] = 0.f; aw1[j] = 0.f; aw2[j] = 0.f; aS[j] = 0.f; }

    const float* vs = Vs + m * 3 * N;
    const float* Rm = g_R + m * 9;
    float r0 = Rm[0], r1 = Rm[1], r2c = Rm[2], r3 = Rm[3], r4 = Rm[4], r5 = Rm[5],
          r6 = Rm[6], r7 = Rm[7], r8 = Rm[8];
    float tt0 = g_t[m * 3 + 0], tt1 = g_t[m * 3 + 1], tt2 = g_t[m * 3 + 2];

#pragma unroll 2
    for (int n = n0; n < n0 + 16; n++) {
        float v0 = vs[n], v1 = vs[N + n], v2 = vs[2 * N + n];
        float tx = fmaf(r0, v0, fmaf(r1, v1, fmaf(r2c, v2, tt0)));
        float ty = fmaf(r3, v0, fmaf(r4, v1, fmaf(r5, v2, tt1)));
        float tz = fmaf(r6, v0, fmaf(r7, v1, fmaf(r8, v2, tt2)));
        float rr = fmaf(tx, tx, fmaf(ty, ty, tz * tz));
        float vv = fmaf(v0, v0, fmaf(v1, v1, v2 * v2));
        float ap[8]; float s = 0.f;
#pragma unroll
        for (int j = 0; j < 8; j++) {
            float arg = fmaf(cx[j], tx, fmaf(cy[j], ty, fmaf(cz[j], tz, fmaf(nq[j], rr, cc[j]))));
            float e = ex2f(arg) * q15[j];
            ap[j] = e; s += e;
        }
        WSUM(s);
        float inv = 1.f / (s + beta);
#pragma unroll
        for (int j = 0; j < 8; j++) {
            float av = ap[j] * inv;
            accL[j] += av;
            aw0[j] = fmaf(v0, av, aw0[j]);
            aw1[j] = fmaf(v1, av, aw1[j]);
            aw2[j] = fmaf(v2, av, aw2[j]);
            aS[j]  = fmaf(vv, av, aS[j]);
        }
    }
    __shared__ float sh[5 * KC];
    for (int i = threadIdx.x; i < 5 * KC; i += 128) sh[i] = 0.f;
    __syncthreads();
#pragma unroll
    for (int j = 0; j < 8; j++) {
        int k = lane + (j << 5);
        atomicAdd(&sh[k], accL[j]);
        atomicAdd(&sh[KC + k], aw0[j]);
        atomicAdd(&sh[2 * KC + k], aw1[j]);
        atomicAdd(&sh[3 * KC + k], aw2[j]);
        atomicAdd(&sh[4 * KC + k], aS[j]);
    }
    __syncthreads();
    for (int i = threadIdx.x; i < KC; i += 128) {
        atomicAdd(&g_L[m * KC + i], sh[i]);
        atomicAdd(&g_W[(m * 3 + 0) * KC + i], sh[KC + i]);
        atomicAdd(&g_W[(m * 3 + 1) * KC + i], sh[2 * KC + i]);
        atomicAdd(&g_W[(m * 3 + 2) * KC + i], sh[3 * KC + i]);
        atomicAdd(&g_S2v[m * KC + i], sh[4 * KC + i]);
    }
}

// Jacobi rotation with COMPILE-TIME indices (keeps A/V in registers)
#define JROT(P_, Q_) do { \
    float apq = A[P_][Q_]; \
    if (fabsf(apq) > 1e-30f) { \
        float theta = 0.5f * (A[Q_][Q_] - A[P_][P_]) / apq; \
        float tj = copysignf(1.f, theta) / (fabsf(theta) + sqrtf(fmaf(theta, theta, 1.f))); \
        float c = rsqrtf(fmaf(tj, tj, 1.f)); \
        float sj = tj * c; \
        _Pragma("unroll") \
        for (int i_ = 0; i_ < 3; i_++) { \
            float aip = A[i_][P_], aiq = A[i_][Q_]; \
            A[i_][P_] = c * aip - sj * aiq; \
            A[i_][Q_] = sj * aip + c * aiq; \
        } \
        _Pragma("unroll") \
        for (int i_ = 0; i_ < 3; i_++) { \
            float api = A[P_][i_], aqi = A[Q_][i_]; \
            A[P_][i_] = c * api - sj * aqi; \
            A[Q_][i_] = sj * api + c * aqi; \
        } \
        _Pragma("unroll") \
        for (int i_ = 0; i_ < 3; i_++) { \
            float vip = V[i_][P_], viq = V[i_][Q_]; \
            V[i_][P_] = c * vip - sj * viq; \
            V[i_][Q_] = sj * vip + c * viq; \
        } \
    } \
} while (0)

#define VSWAPC(C0_, C1_) do { \
    float tmp_; \
    tmp_ = V[0][C0_]; V[0][C0_] = V[0][C1_]; V[0][C1_] = tmp_; \
    tmp_ = V[1][C0_]; V[1][C0_] = V[1][C1_]; V[1][C1_] = tmp_; \
    tmp_ = V[2][C0_]; V[2][C0_] = V[2][C1_]; V[2][C1_] = tmp_; \
} while (0)

// ---- solve: moments -> SVD -> R,t ; then per-k T/S2 -> X,Q update -------
__global__ void k_solve(int iter) {
    __shared__ float sR[M][9], st[M][3];
    int t = threadIdx.x;
    int lane = t & 31, m = t >> 5;   // warp m handles point set m
    float mW0 = 0, mW1 = 0, mW2 = 0, z = 0, mX0 = 0, mX1 = 0, mX2 = 0;
    float p[9];
#pragma unroll
    for (int i = 0; i < 9; i++) p[i] = 0.f;
#pragma unroll
    for (int j = 0; j < 8; j++) {
        int k = lane + (j << 5);
        float L = g_L[m * KC + k];
        float q = g_Q[k];
        float4 xx = g_X[k];
        float w0 = g_W[(m * 3 + 0) * KC + k] * q;
        float w1 = g_W[(m * 3 + 1) * KC + k] * q;
        float w2 = g_W[(m * 3 + 2) * KC + k] * q;
        mW0 += w0; mW1 += w1; mW2 += w2;
        float b = L * q; z += b;
        mX0 = fmaf(b, xx.x, mX0); mX1 = fmaf(b, xx.y, mX1); mX2 = fmaf(b, xx.z, mX2);
        p[0] = fmaf(w0, xx.x, p[0]); p[1] = fmaf(w1, xx.x, p[1]); p[2] = fmaf(w2, xx.x, p[2]);
        p[3] = fmaf(w0, xx.y, p[3]); p[4] = fmaf(w1, xx.y, p[4]); p[5] = fmaf(w2, xx.y, p[5]);
        p[6] = fmaf(w0, xx.z, p[6]); p[7] = fmaf(w1, xx.z, p[7]); p[8] = fmaf(w2, xx.z, p[8]);
    }
    WSUM(mW0); WSUM(mW1); WSUM(mW2); WSUM(z); WSUM(mX0); WSUM(mX1); WSUM(mX2);
#pragma unroll
    for (int i = 0; i < 9; i++) WSUM(p[i]);

    if (lane == 0) {
        float iz = 1.f / z;
        float mXa[3] = { mX0, mX1, mX2 }, mWa[3] = { mW0, mW1, mW2 };
        float P[3][3];
#pragma unroll
        for (int e = 0; e < 3; e++)
#pragma unroll
            for (int d = 0; d < 3; d++)
                P[e][d] = p[e * 3 + d] - mXa[e] * mWa[d] * iz;
        float A[3][3];
#pragma unroll
        for (int d1 = 0; d1 < 3; d1++)
#pragma unroll
            for (int d2 = 0; d2 < 3; d2++) {
                float s2 = 0.f;
#pragma unroll
                for (int e = 0; e < 3; e++) s2 += P[e][d1] * P[e][d2];
                A[d1][d2] = s2;
            }
        float V[3][3] = { {1, 0, 0}, {0, 1, 0}, {0, 0, 1} };
#pragma unroll
        for (int sweep = 0; sweep < 8; sweep++) {
            JROT(0, 1);
            JROT(0, 2);
            JROT(1, 2);
        }
        float e0 = A[0][0], e1 = A[1][1], e2 = A[2][2];
        if (e0 < e1) { float tm = e0; e0 = e1; e1 = tm; VSWAPC(0, 1); }
        if (e1 < e2) { float tm = e1; e1 = e2; e2 = tm; VSWAPC(1, 2); }
        if (e0 < e1) { float tm = e0; e0 = e1; e1 = tm; VSWAPC(0, 1); }
        float det = V[0][0] * (V[1][1] * V[2][2] - V[1][2] * V[2][1])
                  - V[0][1] * (V[1][0] * V[2][2] - V[1][2] * V[2][0])
                  + V[0][2] * (V[1][0] * V[2][1] - V[1][1] * V[2][0]);
        if (det < 0.f) { V[0][2] = -V[0][2]; V[1][2] = -V[1][2]; V[2][2] = -V[2][2]; }
        float u1[3], u2[3], u3[3];
#pragma unroll
        for (int e = 0; e < 3; e++) {
            u1[e] = P[e][0] * V[0][0] + P[e][1] * V[1][0] + P[e][2] * V[2][0];
            u2[e] = P[e][0] * V[0][1] + P[e][1] * V[1][1] + P[e][2] * V[2][1];
        }
        float n1 = rsqrtf(u1[0] * u1[0] + u1[1] * u1[1] + u1[2] * u1[2]);
#pragma unroll
        for (int e = 0; e < 3; e++) u1[e] *= n1;
        float d12 = u1[0] * u2[0] + u1[1] * u2[1] + u1[2] * u2[2];
#pragma unroll
        for (int e = 0; e < 3; e++) u2[e] -= d12 * u1[e];
        float n2 = rsqrtf(u2[0] * u2[0] + u2[1] * u2[1] + u2[2] * u2[2]);
#pragma unroll
        for (int e = 0; e < 3; e++) u2[e] *= n2;
        u3[0] = u1[1] * u2[2] - u1[2] * u2[1];
        u3[1] = u1[2] * u2[0] - u1[0] * u2[2];
        u3[2] = u1[0] * u2[1] - u1[1] * u2[0];
        float R[9];
#pragma unroll
        for (int i = 0; i < 3; i++)
#pragma unroll
            for (int jj = 0; jj < 3; jj++)
                R[i * 3 + jj] = u1[i] * V[jj][0] + u2[i] * V[jj][1] + u3[i] * V[jj][2];
#pragma unroll
        for (int i = 0; i < 9; i++) { g_R[m * 9 + i] = R[i]; sR[m][i] = R[i]; }
#pragma unroll
        for (int i = 0; i < 3; i++) {
            float tv = (mXa[i] - (R[i * 3 + 0] * mW0 + R[i * 3 + 1] * mW1 + R[i * 3 + 2] * mW2)) * iz;
            g_t[m * 3 + i] = tv; st[m][i] = tv;
        }
    }
    __syncthreads();

    // ---- per-k: den, T = sum_m (R Wraw + t L), S2; then X/Q update ----
    if (t < KC) {
        float den = 0.f, T0 = 0.f, T1 = 0.f, T2 = 0.f, S2 = 0.f;
#pragma unroll
        for (int mm = 0; mm < M; mm++) {
            float L  = g_L[mm * KC + t];
            float w0 = g_W[(mm * 3 + 0) * KC + t];
            float w1 = g_W[(mm * 3 + 1) * KC + t];
            float w2 = g_W[(mm * 3 + 2) * KC + t];
            float s2v = g_S2v[mm * KC + t];
            float t0 = st[mm][0], t1 = st[mm][1], t2 = st[mm][2];
            float rw0 = sR[mm][0] * w0 + sR[mm][1] * w1 + sR[mm][2] * w2;
            float rw1 = sR[mm][3] * w0 + sR[mm][4] * w1 + sR[mm][5] * w2;
            float rw2 = sR[mm][6] * w0 + sR[mm][7] * w1 + sR[mm][8] * w2;
            den += L;
            T0 += rw0 + t0 * L; T1 += rw1 + t1 * L; T2 += rw2 + t2 * L;
            S2 += s2v + 2.f * (t0 * rw0 + t1 * rw1 + t2 * rw2)
                + (t0 * t0 + t1 * t1 + t2 * t2) * L;
        }
        float inv = 1.f / den;
        float wn;
        if (iter > 1) {                          // FIX_CLUSTER_POS_ITER = 1
            float x = T0 * inv, y = T1 * inv, zz = T2 * inv;
            float xw = x * x + y * y + zz * zz;
            wn = S2 - (T0 * T0 + T1 * T1 + T2 * T2) * inv;
            g_X[t] = make_float4(x, y, zz, xw);
        } else {
            float4 xo = g_X[t];
            wn = fmaf(den, xo.w, S2) - 2.f * (xo.x * T0 + xo.y * T1 + xo.z * T2);
        }
        g_Q[t] = 3.f * den / (wn + 3.f * den * EPSILON);
    }
    __syncthreads();
    for (int i = t; i < M * KC; i += 256) { g_L[i] = 0.f; g_S2v[i] = 0.f; }
    for (int i = t; i < M * 3 * KC; i += 256) g_W[i] = 0.f;
}

// ---------------- gather outputs: concat(TVs, R, t, X) -------------------
__global__ void k_out(float* out, const float* __restrict__ Vs) {
    int idx = blockIdx.x * 256 + threadIdx.x;
    const int nTV = M * 3 * N, nR = M * 9, nT = M * 3, nX = KC * 3;
    if (idx < nTV) {
        int md = idx / N, n = idx - md * N;
        int m = md / 3, d = md - 3 * m;
        const float* v = Vs + m * 3 * N;
        const float* R = g_R + m * 9 + d * 3;
        out[idx] = fmaf(R[0], v[n], fmaf(R[1], v[N + n], fmaf(R[2], v[2 * N + n], g_t[md])));
    } else if (idx < nTV + nR) out[idx] = g_R[idx - nTV];
    else if (idx < nTV + nR + nT) out[idx] = g_t[idx - nTV - nR];
    else if (idx < nTV + nR + nT + nX) {
        int r = idx - nTV - nR - nT;
        int k = r / 3, d = r - 3 * k;
        float4 xx = g_X[k];
        out[idx] = (d == 0) ? xx.x : ((d == 1) ? xx.y : xx.z);
    }
}

extern "C" void kernel_launch(void* const* d_in, const int* in_sizes, int n_in,
                              void* d_out, int out_size) {
    const float* Vs = (const float*)d_in[0];
    const float* X0 = (const float*)d_in[1];
    const float* Q0 = (const float*)d_in[2];
    float* out = (float*)d_out;

    k_pre<<<25, 256>>>(Vs, X0, Q0);

    for (int i = 0; i < ITERS; i++) {
        k_apass<<<1024, 128>>>(Vs);
        k_solve<<<1, 256>>>(i);
    }
    int total = M * 3 * N + M * 9 + M * 3 + KC * 3;
    k_out<<<(total + 255) / 256, 256>>>(out, Vs);
}